// round 1
// baseline (speedup 1.0000x reference)
#include <cuda_runtime.h>

// DenseTNT postprocess: per-batch greedy NMS over 4096 goal candidates.
// Exact equivalence to sorted-scan NMS: k-th pick = argmax score among
// candidates not suppressed (d2 < 4.0) by the already-picked goals.
// Tie-break: equal score -> lower original index (matches stable argsort).

#define B_       128
#define N_       4096
#define P_       30
#define MODES_   6
#define THRESH2_ 4.0f
#define TPB_     256
#define PER_     (N_ / TPB_)   // 16 candidates per thread

__global__ __launch_bounds__(TPB_, 1)
void densetnt_nms_kernel(const float* __restrict__ scores,   // [B, N]
                         const float* __restrict__ trajs,    // [B, 60, N]
                         const float* __restrict__ goals,    // [B, 2, N]
                         float* __restrict__ out)            // [B,6,30,2] ++ [B,6]
{
    const int b = blockIdx.x;
    const int t = threadIdx.x;

    const float* sc = scores + (size_t)b * N_;
    const float* gx = goals  + (size_t)b * 2 * N_;
    const float* gy = gx + N_;

    // Register-resident candidate state (coalesced loads: idx = t + j*TPB)
    float s[PER_], x[PER_], y[PER_];
#pragma unroll
    for (int j = 0; j < PER_; j++) {
        int i = t + j * TPB_;
        s[j] = sc[i];
        x[j] = gx[i];
        y[j] = gy[i];
    }
    unsigned alive = 0xFFFFu;

    __shared__ unsigned long long red[TPB_ / 32];
    __shared__ float wx_s, wy_s;
    __shared__ int   sel_idx_s[MODES_];
    __shared__ float sel_score_s[MODES_];

    for (int m = 0; m < MODES_; m++) {
        // --- local argmax over alive candidates ---
        unsigned long long best = 0ull;  // 0 = "nothing alive" sentinel
#pragma unroll
        for (int j = 0; j < PER_; j++) {
            if (alive & (1u << j)) {
                unsigned u  = __float_as_uint(s[j]);
                unsigned os = (u & 0x80000000u) ? ~u : (u | 0x80000000u); // order-preserving
                unsigned idx = (unsigned)(t + j * TPB_);
                unsigned long long key =
                    ((unsigned long long)os << 32) | (unsigned long long)(0xFFFFFFFFu - idx);
                best = key > best ? key : best;
            }
        }
        // --- warp reduce ---
#pragma unroll
        for (int o = 16; o > 0; o >>= 1) {
            unsigned long long v = __shfl_xor_sync(0xFFFFFFFFu, best, o);
            best = v > best ? v : best;
        }
        if ((t & 31) == 0) red[t >> 5] = best;
        __syncthreads();
        if (t < 32) {
            unsigned long long v = (t < TPB_ / 32) ? red[t] : 0ull;
#pragma unroll
            for (int o = 4; o > 0; o >>= 1) {
                unsigned long long w = __shfl_xor_sync(0xFFFFFFFFu, v, o);
                v = w > v ? w : v;
            }
            if (t == 0) red[0] = v;
        }
        __syncthreads();
        const unsigned long long win = red[0];  // block-uniform

        if (win == 0ull) {
            // everything suppressed: fall back to slot 0 (top-scored candidate)
            if (t == 0) {
                sel_idx_s[m]   = sel_idx_s[0];
                sel_score_s[m] = sel_score_s[0];
            }
        } else {
            const int widx = (int)(0xFFFFFFFFu - (unsigned)(win & 0xFFFFFFFFull));
            // decode score
            unsigned os = (unsigned)(win >> 32);
            unsigned su = (os & 0x80000000u) ? (os & 0x7FFFFFFFu) : ~os;
            const float wscore = __uint_as_float(su);

            // owner thread publishes the winning goal
            if (t == (widx & (TPB_ - 1))) {
                int j = widx / TPB_;
                wx_s = x[j];
                wy_s = y[j];
                sel_idx_s[m]   = widx;
                sel_score_s[m] = wscore;
            }
            __syncthreads();   // block-uniform branch: legal
            const float wxv = wx_s, wyv = wy_s;
#pragma unroll
            for (int j = 0; j < PER_; j++) {
                float dx = x[j] - wxv;
                float dy = y[j] - wyv;
                if (dx * dx + dy * dy < THRESH2_) alive &= ~(1u << j);
            }
        }
        __syncthreads();
    }

    // --- gather outputs ---
    // trajectories: out[(b*6 + m)*60 + k] = trajs[b*60*N + k*N + sel_idx[m]]
    const float* tb = trajs + (size_t)b * 60 * N_;
    float* ob = out + (size_t)b * MODES_ * 60;
    for (int e = t; e < MODES_ * 60; e += TPB_) {
        int m = e / 60;
        int k = e - m * 60;
        ob[e] = tb[(size_t)k * N_ + sel_idx_s[m]];
    }
    // scores: appended after all trajectories
    if (t < MODES_) {
        out[(size_t)B_ * MODES_ * 60 + (size_t)b * MODES_ + t] = sel_score_s[t];
    }
}

extern "C" void kernel_launch(void* const* d_in, const int* in_sizes, int n_in,
                              void* d_out, int out_size)
{
    const float* goals_scores = (const float*)d_in[0];  // [128, 4096]
    const float* traj_preds   = (const float*)d_in[1];  // [128, 60, 4096]
    const float* pred_goals   = (const float*)d_in[2];  // [128, 2, 4096]
    float* out = (float*)d_out;

    densetnt_nms_kernel<<<B_, TPB_>>>(goals_scores, traj_preds, pred_goals, out);
}

// round 2
// speedup vs baseline: 1.0238x; 1.0238x over previous
#include <cuda_runtime.h>

// DenseTNT postprocess: per-batch greedy NMS over 4096 goal candidates.
// Exact equivalence to sorted-scan NMS: k-th pick = argmax score among
// candidates not suppressed (d2 < 4.0) by already-picked goals.
// Tie-break: equal score -> lower original index (stable argsort semantics),
// encoded in a 64-bit key = (ordered_float(score) << 32) | (~idx).

#define B_       128
#define N_       4096
#define MODES_   6
#define THRESH2_ 4.0f
#define TPB_     512
#define PER_     (N_ / TPB_)   // 8 candidates per thread
#define NW_      (TPB_ / 32)   // 16 warps

__global__ __launch_bounds__(TPB_, 1)
void densetnt_nms_kernel(const float* __restrict__ scores,   // [B, N]
                         const float* __restrict__ trajs,    // [B, 60, N]
                         const float* __restrict__ goals,    // [B, 2, N]
                         float* __restrict__ out)            // [B,6,30,2] ++ [B,6]
{
    const int b    = blockIdx.x;
    const int t    = threadIdx.x;
    const int w    = t >> 5;
    const int lane = t & 31;

    __shared__ float2 sgoal[N_];                       // 32 KB goal mirror
    __shared__ unsigned long long red[2][NW_];         // parity double-buffer
    __shared__ unsigned long long win_s[MODES_];
    __shared__ int   sel_s[MODES_];
    __shared__ float ssc_s[MODES_];

    const float* sc = scores + (size_t)b * N_;
    const float* gx = goals  + (size_t)b * 2 * N_;
    const float* gy = gx + N_;

    // Load candidates; build 64-bit argmax keys once.
    unsigned long long key[PER_];
    float x[PER_], y[PER_];
#pragma unroll
    for (int j = 0; j < PER_; j++) {
        int i = t + j * TPB_;
        float s = sc[i];
        x[j] = gx[i];
        y[j] = gy[i];
        sgoal[i] = make_float2(x[j], y[j]);
        unsigned u  = __float_as_uint(s);
        unsigned os = (u & 0x80000000u) ? ~u : (u | 0x80000000u);  // order-preserving
        key[j] = ((unsigned long long)os << 32)
               | (unsigned long long)(0xFFFFFFFFu - (unsigned)i);
    }
    __syncthreads();

    for (int m = 0; m < MODES_; m++) {
        // local argmax (killed candidates have key==0)
        unsigned long long best = 0ull;
#pragma unroll
        for (int j = 0; j < PER_; j++) best = key[j] > best ? key[j] : best;

        // warp reduce
#pragma unroll
        for (int o = 16; o > 0; o >>= 1) {
            unsigned long long v = __shfl_xor_sync(0xFFFFFFFFu, best, o);
            best = v > best ? v : best;
        }
        if (lane == 0) red[m & 1][w] = best;
        __syncthreads();   // ONLY barrier this round

        // every thread reduces the 16 warp partials (broadcast LDS, no 2nd sync)
        unsigned long long win = 0ull;
#pragma unroll
        for (int ww = 0; ww < NW_; ww++) {
            unsigned long long v = red[m & 1][ww];
            win = v > win ? v : win;
        }
        if (t == 0) win_s[m] = win;

        if (win != 0ull) {
            const int widx = (int)(0xFFFFFFFFu - (unsigned)(win & 0xFFFFFFFFull));
            const float2 g = sgoal[widx];      // broadcast read
#pragma unroll
            for (int j = 0; j < PER_; j++) {
                float dx = x[j] - g.x;
                float dy = y[j] - g.y;
                if (dx * dx + dy * dy < THRESH2_) key[j] = 0ull;
            }
        }
        // no barrier here: next round's STS goes to the other parity buffer,
        // and the round-(m+1) barrier bounds skew to one round.
    }
    __syncthreads();   // win_s complete

    // decode selections (fallback: empty slot -> round-0 winner = global top-1)
    if (t < MODES_) {
        unsigned long long wv = win_s[t];
        if (wv == 0ull) wv = win_s[0];
        sel_s[t] = (int)(0xFFFFFFFFu - (unsigned)(wv & 0xFFFFFFFFull));
        unsigned os = (unsigned)(wv >> 32);
        unsigned su = (os & 0x80000000u) ? (os & 0x7FFFFFFFu) : ~os;
        ssc_s[t] = __uint_as_float(su);
    }
    __syncthreads();

    // gather: out trajs [B,6,30,2] then scores [B,6]
    const float* tb = trajs + (size_t)b * 60 * N_;
    float* ob = out + (size_t)b * MODES_ * 60;
    for (int e = t; e < MODES_ * 60; e += TPB_) {
        int m = e / 60;
        int k = e - m * 60;
        ob[e] = __ldg(tb + (size_t)k * N_ + sel_s[m]);
    }
    if (t < MODES_) {
        out[(size_t)B_ * MODES_ * 60 + (size_t)b * MODES_ + t] = ssc_s[t];
    }
}

extern "C" void kernel_launch(void* const* d_in, const int* in_sizes, int n_in,
                              void* d_out, int out_size)
{
    const float* goals_scores = (const float*)d_in[0];  // [128, 4096]
    const float* traj_preds   = (const float*)d_in[1];  // [128, 60, 4096]
    const float* pred_goals   = (const float*)d_in[2];  // [128, 2, 4096]
    float* out = (float*)d_out;

    densetnt_nms_kernel<<<B_, TPB_>>>(goals_scores, traj_preds, pred_goals, out);
}